// round 4
// baseline (speedup 1.0000x reference)
#include <cuda_runtime.h>
#include <math.h>

// Problem constants
#define BB 2
#define NN 512
#define CC 151
#define DD 4096
#define SCORE_THRESH 0.05f
#define NMS_THRESH 0.5
#define TOPN_PER_CLS 300
#define DET_PER_IMG 100
#define W_CLIP 799.0f
#define H_CLIP 599.0f

#define GRID 148
#define TPB  512

// input element counts (for pointer identification)
#define SZ_LOGITS (BB*NN*CC)       // 154624
#define SZ_REG    (BB*NN*CC*4)     // 618496
#define SZ_PROPS  (BB*NN*4)        // 4096
#define SZ_FEATS  (BB*NN*DD)       // 4194304

// output layout (float32)
#define OFF_BOXES  0
#define OFF_SCORES (BB*NN*4)            // 4096
#define OFF_LABELS (OFF_SCORES + BB*NN) // 5120
#define OFF_VALID  (OFF_LABELS + BB*NN) // 6144
#define OFF_FEATS  (OFF_VALID + BB*NN)  // 7168

// scratch (device globals; no allocation allowed)
__device__ float g_prob[BB*CC*NN];   // [b][c][n]
__device__ float g_dist[BB*CC*NN];   // [b][c][n]  kept score or 0
__device__ float g_validf[BB*NN];    // 1.0/0.0 mask for features

// grid barrier state (monotone generation; survives graph replays)
__device__ unsigned g_count = 0;
__device__ unsigned g_gen   = 0;

__device__ __forceinline__ void grid_sync()
{
    __syncthreads();
    if (threadIdx.x == 0) {
        __threadfence();
        unsigned gen = *(volatile unsigned*)&g_gen;
        if (atomicAdd(&g_count, 1u) == GRID - 1u) {
            atomicExch(&g_count, 0u);
            __threadfence();
            atomicAdd(&g_gen, 1u);
        } else {
            while (*(volatile unsigned*)&g_gen == gen) { }
        }
        __threadfence();
    }
    __syncthreads();
}

// ---------------------------------------------------------------------------
// helpers (decode/IoU in double: decision-critical geometry, ~6K calls only)
// ---------------------------------------------------------------------------
__device__ __forceinline__ void decode_clip(const float* pb, const float* rg,
                                            float& X1, float& Y1, float& X2, float& Y2)
{
    const double DCLAMP = (double)(float)log(62.5);  // float(np.log(1000/16))
    double x1 = pb[0], y1 = pb[1], x2 = pb[2], y2 = pb[3];
    double w = x2 - x1 + 1.0, h = y2 - y1 + 1.0;
    double cx = x1 + 0.5 * w, cy = y1 + 0.5 * h;
    double dx = (double)rg[0] / 10.0;
    double dy = (double)rg[1] / 10.0;
    double dw = fmin((double)rg[2] / 5.0, DCLAMP);
    double dh = fmin((double)rg[3] / 5.0, DCLAMP);
    double pcx = dx * w + cx, pcy = dy * h + cy;
    double pw = exp(dw) * w, ph = exp(dh) * h;
    float a = (float)(pcx - 0.5 * pw);
    float b = (float)(pcy - 0.5 * ph);
    float c = (float)(pcx + 0.5 * pw - 1.0);
    float d = (float)(pcy + 0.5 * ph - 1.0);
    X1 = fminf(fmaxf(a, 0.f), W_CLIP);
    Y1 = fminf(fmaxf(b, 0.f), H_CLIP);
    X2 = fminf(fmaxf(c, 0.f), W_CLIP);
    Y2 = fminf(fmaxf(d, 0.f), H_CLIP);
}

__device__ __forceinline__ double iou_d(float ax1, float ay1, float ax2, float ay2,
                                        float bx1, float by1, float bx2, float by2)
{
    double areaA = ((double)ax2 - (double)ax1 + 1.0) * ((double)ay2 - (double)ay1 + 1.0);
    double areaB = ((double)bx2 - (double)bx1 + 1.0) * ((double)by2 - (double)by1 + 1.0);
    double xx1 = fmax((double)ax1, (double)bx1);
    double yy1 = fmax((double)ay1, (double)by1);
    double xx2 = fmin((double)ax2, (double)bx2);
    double yy2 = fmin((double)ay2, (double)by2);
    double iw = fmax(xx2 - xx1 + 1.0, 0.0);
    double ih = fmax(yy2 - yy1 + 1.0, 0.0);
    double inter = iw * ih;
    return inter / (areaA + areaB - inter);
}

// shared memory shared across phases
struct SmemNMS {
    int   cnt;
    float cs[NN];
    int   cn[NN];
    float bx1[NN], by1[NN], bx2[NN], by2[NN];
    int   ord[NN];
    unsigned char keep[NN];
};
struct SmemSel {
    int   cnt;
    float ss[NN];
};
union SmemAll {
    SmemNMS nms;
    SmemSel sel;
};

// ---------------------------------------------------------------------------
// single persistent kernel: softmax -> NMS -> select -> feature mask
// ---------------------------------------------------------------------------
__global__ __launch_bounds__(TPB, 1) void k_all(const float* __restrict__ logits,
                                                const float* __restrict__ reg,
                                                const float* __restrict__ props,
                                                const float4* __restrict__ feats,
                                                float* __restrict__ out)
{
    __shared__ SmemAll sm;
    const int tid  = threadIdx.x;
    const int lane = tid & 31;
    const int wid  = tid >> 5;

    // ---------------- Phase A: softmax, one warp per (b,n) row -------------
    {
        int gw = blockIdx.x * (TPB / 32) + wid;      // 2368 warps >= 1024 rows
        if (gw < BB * NN) {
            int b = gw >> 9, n = gw & 511;
            const float* lrow = logits + gw * CC;
            float x[5];
            float m = -INFINITY;
            #pragma unroll
            for (int j = 0; j < 5; j++) {
                int c = lane + 32 * j;
                x[j] = (c < CC) ? lrow[c] : -INFINITY;
                m = fmaxf(m, x[j]);
            }
            #pragma unroll
            for (int s = 16; s > 0; s >>= 1)
                m = fmaxf(m, __shfl_xor_sync(0xffffffffu, m, s));
            float e[5], sum = 0.f;
            #pragma unroll
            for (int j = 0; j < 5; j++) {
                int c = lane + 32 * j;
                e[j] = (c < CC) ? expf(x[j] - m) : 0.f;
                sum += e[j];
            }
            #pragma unroll
            for (int s = 16; s > 0; s >>= 1)
                sum += __shfl_xor_sync(0xffffffffu, sum, s);
            float inv = 1.f / sum;
            #pragma unroll
            for (int j = 0; j < 5; j++) {
                int c = lane + 32 * j;
                if (c < CC)
                    g_prob[((b * CC + c) << 9) + n] = e[j] * inv;
            }
        }
    }
    grid_sync();

    // ---------------- Phase B: per-(b,c) NMS -------------------------------
    for (int task = blockIdx.x; task < BB * CC; task += GRID) {
        __syncthreads();                      // protect smem reuse across tasks
        int b = task / CC, c = task % CC;
        const float* prow = g_prob + task * NN;
        float* drow = g_dist + task * NN;

        float s = prow[tid];
        drow[tid] = 0.f;
        if (c != 0) {
            if (tid == 0) sm.nms.cnt = 0;
            __syncthreads();

            int slot = -1;
            if (s > SCORE_THRESH) slot = atomicAdd(&sm.nms.cnt, 1);
            if (slot >= 0) { sm.nms.cs[slot] = s; sm.nms.cn[slot] = tid; }
            __syncthreads();

            int M = sm.nms.cnt;
            if (M > 0) {
                if (tid < M) {
                    int n = sm.nms.cn[tid];
                    const float* pb = props + (b * NN + n) * 4;
                    const float* rg = reg + (size_t)(((b * NN + n) * CC) + c) * 4;
                    decode_clip(pb, rg, sm.nms.bx1[tid], sm.nms.by1[tid],
                                sm.nms.bx2[tid], sm.nms.by2[tid]);
                    sm.nms.keep[tid] = 1;
                    sm.nms.ord[tid] = tid;
                }
                int P = 1;
                while (P < M) P <<= 1;
                if (tid >= M && tid < P) {
                    sm.nms.cs[tid] = -INFINITY;
                    sm.nms.cn[tid] = 1 << 30;
                    sm.nms.ord[tid] = tid;
                }
                __syncthreads();

                // bitonic argsort: descending score, ascending original index
                for (int k = 2; k <= P; k <<= 1) {
                    for (int j = k >> 1; j > 0; j >>= 1) {
                        if (tid < P) {
                            int ixj = tid ^ j;
                            if (ixj > tid) {
                                int a = sm.nms.ord[tid], bo = sm.nms.ord[ixj];
                                float sa = sm.nms.cs[a], sb = sm.nms.cs[bo];
                                bool pa = (sa > sb) || (sa == sb && sm.nms.cn[a] < sm.nms.cn[bo]);
                                bool desc = ((tid & k) == 0);
                                bool sw = desc ? !pa : pa;
                                if (sw) { sm.nms.ord[tid] = bo; sm.nms.ord[ixj] = a; }
                            }
                        }
                        __syncthreads();
                    }
                }

                // greedy NMS in sorted order
                for (int i = 0; i < M - 1; i++) {
                    __syncthreads();
                    int oi = sm.nms.ord[i];
                    if (!sm.nms.keep[oi]) continue;   // shared: uniform branch
                    float ax1 = sm.nms.bx1[oi], ay1 = sm.nms.by1[oi];
                    float ax2 = sm.nms.bx2[oi], ay2 = sm.nms.by2[oi];
                    for (int t = i + 1 + tid; t < M; t += TPB) {
                        int ot = sm.nms.ord[t];
                        if (!sm.nms.keep[ot]) continue;
                        double iou = iou_d(ax1, ay1, ax2, ay2,
                                           sm.nms.bx1[ot], sm.nms.by1[ot],
                                           sm.nms.bx2[ot], sm.nms.by2[ot]);
                        if (iou > NMS_THRESH) sm.nms.keep[ot] = 0;
                    }
                }
                __syncthreads();

                // per-class top-300 cap in sorted order
                if (tid == 0) {
                    int cum = 0;
                    for (int t = 0; t < M; t++) {
                        int ot = sm.nms.ord[t];
                        if (sm.nms.keep[ot]) { if (++cum > TOPN_PER_CLS) sm.nms.keep[ot] = 0; }
                    }
                }
                __syncthreads();

                if (tid < M && sm.nms.keep[tid]) drow[sm.nms.cn[tid]] = sm.nms.cs[tid];
            }
        }
    }
    grid_sync();

    // ---------------- Phase C: per-image select (blocks 0..BB-1) -----------
    if (blockIdx.x < BB) {
        int b = blockIdx.x;
        int n = tid;

        float best = 0.f; int lab = 0;
        const float* dbase = g_dist + (size_t)b * CC * NN + n;
        #pragma unroll 4
        for (int c = 1; c < CC; c++) {
            float d = dbase[c << 9];
            if (d > best) { best = d; lab = c; }     // strict > = first-index argmax
        }
        bool v0 = best > 0.f;

        if (n == 0) sm.sel.cnt = 0;
        __syncthreads();
        sm.sel.ss[n] = v0 ? best : -1.0f;
        if (v0) atomicAdd(&sm.sel.cnt, 1);
        __syncthreads();

        // bitonic descending sort of 512 floats
        for (int k = 2; k <= NN; k <<= 1) {
            for (int j = k >> 1; j > 0; j >>= 1) {
                int ixj = n ^ j;
                if (ixj > n) {
                    float a = sm.sel.ss[n], bb2 = sm.sel.ss[ixj];
                    bool desc = ((n & k) == 0);
                    bool sw = desc ? (a < bb2) : (a > bb2);
                    if (sw) { sm.sel.ss[n] = bb2; sm.sel.ss[ixj] = a; }
                }
                __syncthreads();
            }
        }
        float kth = sm.sel.ss[DET_PER_IMG - 1];
        float thr = (sm.sel.cnt > DET_PER_IMG) ? kth : -1.0f;
        bool det = v0 && (best >= thr);

        float X1 = 0.f, Y1 = 0.f, X2 = 0.f, Y2 = 0.f, sc = 0.f, lb = 0.f, dv = 0.f;
        if (det) {
            const float* pb = props + (b * NN + n) * 4;
            const float* rg = reg + (size_t)(((b * NN + n) * CC) + lab) * 4;
            decode_clip(pb, rg, X1, Y1, X2, Y2);
            sc = best; lb = (float)lab; dv = 1.f;
        }
        int idx = b * NN + n;
        out[OFF_BOXES + idx * 4 + 0] = X1;
        out[OFF_BOXES + idx * 4 + 1] = Y1;
        out[OFF_BOXES + idx * 4 + 2] = X2;
        out[OFF_BOXES + idx * 4 + 3] = Y2;
        out[OFF_SCORES + idx] = sc;
        out[OFF_LABELS + idx] = lb;
        out[OFF_VALID  + idx] = dv;
        g_validf[idx] = dv;
    }
    grid_sync();

    // ---------------- Phase D: features * det_valid ------------------------
    {
        float4* fout = (float4*)(out + OFF_FEATS);
        int gtid = blockIdx.x * TPB + tid;
        const int NT = GRID * TPB;
        for (int i = gtid; i < SZ_FEATS / 4; i += NT) {
            float m = g_validf[i >> 10];   // DD/4 = 1024 float4 per row
            float4 v = feats[i];
            v.x *= m; v.y *= m; v.z *= m; v.w *= m;
            fout[i] = v;
        }
    }
}

// ---------------------------------------------------------------------------
extern "C" void kernel_launch(void* const* d_in, const int* in_sizes, int n_in,
                              void* d_out, int out_size)
{
    const float *logits = nullptr, *reg = nullptr, *props = nullptr, *feats = nullptr;
    for (int i = 0; i < n_in; i++) {
        switch (in_sizes[i]) {
            case SZ_LOGITS: logits = (const float*)d_in[i]; break;
            case SZ_REG:    reg    = (const float*)d_in[i]; break;
            case SZ_PROPS:  props  = (const float*)d_in[i]; break;
            case SZ_FEATS:  feats  = (const float*)d_in[i]; break;
            default: break;
        }
    }
    float* out = (float*)d_out;
    k_all<<<GRID, TPB>>>(logits, reg, props, (const float4*)feats, out);
    (void)out_size;
}

// round 5
// speedup vs baseline: 2.4739x; 2.4739x over previous
#include <cuda_runtime.h>
#include <math.h>

// Problem constants
#define BB 2
#define NN 512
#define CC 151
#define DD 4096
#define SCORE_THRESH 0.05f
#define NMS_THRESH_F 0.5f
#define TOPN_PER_CLS 300
#define DET_PER_IMG 100
#define W_CLIP 799.0f
#define H_CLIP 599.0f

// input element counts (for pointer identification)
#define SZ_LOGITS (BB*NN*CC)       // 154624
#define SZ_REG    (BB*NN*CC*4)     // 618496
#define SZ_PROPS  (BB*NN*4)        // 4096
#define SZ_FEATS  (BB*NN*DD)       // 4194304

// output layout (float32)
#define OFF_BOXES  0
#define OFF_SCORES (BB*NN*4)            // 4096
#define OFF_LABELS (OFF_SCORES + BB*NN) // 5120
#define OFF_VALID  (OFF_LABELS + BB*NN) // 6144
#define OFF_FEATS  (OFF_VALID + BB*NN)  // 7168

// scratch (device globals; no allocation allowed)
__device__ float g_prob[BB*CC*NN];   // [b][c][n]
__device__ float g_dist[BB*CC*NN];   // [b][c][n]  kept score or 0
__device__ float g_validf[BB*NN];    // 1.0/0.0 mask for features

// ---------------------------------------------------------------------------
// decode stays double (few K calls; feeds output boxes + IoU inputs)
// ---------------------------------------------------------------------------
__device__ __forceinline__ void decode_clip(const float* pb, const float* rg,
                                            float& X1, float& Y1, float& X2, float& Y2)
{
    const double DCLAMP = (double)(float)log(62.5);  // float(np.log(1000/16))
    double x1 = pb[0], y1 = pb[1], x2 = pb[2], y2 = pb[3];
    double w = x2 - x1 + 1.0, h = y2 - y1 + 1.0;
    double cx = x1 + 0.5 * w, cy = y1 + 0.5 * h;
    double dx = (double)rg[0] / 10.0;
    double dy = (double)rg[1] / 10.0;
    double dw = fmin((double)rg[2] / 5.0, DCLAMP);
    double dh = fmin((double)rg[3] / 5.0, DCLAMP);
    double pcx = dx * w + cx, pcy = dy * h + cy;
    double pw = exp(dw) * w, ph = exp(dh) * h;
    float a = (float)(pcx - 0.5 * pw);
    float b = (float)(pcy - 0.5 * ph);
    float c = (float)(pcx + 0.5 * pw - 1.0);
    float d = (float)(pcy + 0.5 * ph - 1.0);
    X1 = fminf(fmaxf(a, 0.f), W_CLIP);
    Y1 = fminf(fmaxf(b, 0.f), H_CLIP);
    X2 = fminf(fmaxf(c, 0.f), W_CLIP);
    Y2 = fminf(fmaxf(d, 0.f), H_CLIP);
}

// float IoU, exact reference formula order (Pascal +1 convention)
__device__ __forceinline__ float iou_f(float ax1, float ay1, float ax2, float ay2, float areaA,
                                       float bx1, float by1, float bx2, float by2, float areaB)
{
    float xx1 = fmaxf(ax1, bx1);
    float yy1 = fmaxf(ay1, by1);
    float xx2 = fminf(ax2, bx2);
    float yy2 = fminf(ay2, by2);
    float inter = fmaxf(xx2 - xx1 + 1.0f, 0.0f) * fmaxf(yy2 - yy1 + 1.0f, 0.0f);
    return inter / (areaA + areaB - inter);
}

// ---------------------------------------------------------------------------
// K1: softmax, one warp per (b,n) row, fp32, shfl reductions
// ---------------------------------------------------------------------------
__global__ __launch_bounds__(256) void k_softmax(const float* __restrict__ logits)
{
    int gw = blockIdx.x * 8 + (threadIdx.x >> 5);   // 128 blocks * 8 warps = 1024 rows
    int lane = threadIdx.x & 31;
    if (gw >= BB * NN) return;
    int b = gw >> 9, n = gw & 511;
    const float* lrow = logits + gw * CC;
    float x[5];
    float m = -INFINITY;
    #pragma unroll
    for (int j = 0; j < 5; j++) {
        int c = lane + 32 * j;
        x[j] = (c < CC) ? lrow[c] : -INFINITY;
        m = fmaxf(m, x[j]);
    }
    #pragma unroll
    for (int s = 16; s > 0; s >>= 1)
        m = fmaxf(m, __shfl_xor_sync(0xffffffffu, m, s));
    float e[5], sum = 0.f;
    #pragma unroll
    for (int j = 0; j < 5; j++) {
        int c = lane + 32 * j;
        e[j] = (c < CC) ? expf(x[j] - m) : 0.f;
        sum += e[j];
    }
    #pragma unroll
    for (int s = 16; s > 0; s >>= 1)
        sum += __shfl_xor_sync(0xffffffffu, sum, s);
    float inv = 1.f / sum;
    #pragma unroll
    for (int j = 0; j < 5; j++) {
        int c = lane + 32 * j;
        if (c < CC)
            g_prob[((b * CC + c) << 9) + n] = e[j] * inv;
    }
}

// ---------------------------------------------------------------------------
// K2: per (b,c) NMS. Warp fast path for M<=32, block fallback otherwise.
// ---------------------------------------------------------------------------
__global__ __launch_bounds__(512) void k_nms(const float* __restrict__ reg,
                                             const float* __restrict__ props)
{
    int blk = blockIdx.x;           // b*CC + c
    int b = blk / CC, c = blk % CC;
    int tid = threadIdx.x;
    int lane = tid & 31;
    int wid = tid >> 5;

    const float* prow = g_prob + blk * NN;
    float* drow = g_dist + blk * NN;

    float s = prow[tid];
    drow[tid] = 0.f;                // default: not kept
    if (c == 0) return;             // background class dropped

    __shared__ int cnt;
    __shared__ float cs[NN];
    __shared__ int   cn[NN];
    __shared__ float bx1[NN], by1[NN], bx2[NN], by2[NN], bar[NN];
    __shared__ int   ord[NN];
    __shared__ unsigned char keep[NN];

    if (tid == 0) cnt = 0;
    __syncthreads();

    int slot = -1;
    if (s > SCORE_THRESH) slot = atomicAdd(&cnt, 1);
    if (slot >= 0) { cs[slot] = s; cn[slot] = tid; }
    __syncthreads();

    int M = cnt;
    if (M == 0) return;

    if (M <= 32) {
        // ---------------- warp fast path: warp 0 only, no block barriers ---
        if (wid != 0) return;
        const unsigned FULL = 0xffffffffu;
        bool act = lane < M;
        float sc = act ? cs[lane] : -INFINITY;
        int   ci = act ? cn[lane] : (1 << 30);
        float x1 = 0.f, y1 = 0.f, x2 = 0.f, y2 = 0.f;
        if (act) {
            const float* pb = props + (b * NN + ci) * 4;
            const float* rg = reg + (size_t)(((b * NN + ci) * CC) + c) * 4;
            decode_clip(pb, rg, x1, y1, x2, y2);
        }
        float area = (x2 - x1 + 1.0f) * (y2 - y1 + 1.0f);

        // rank: descending score, ties -> ascending original index
        int rank = 0;
        #pragma unroll
        for (int j = 0; j < 32; j++) {
            float sj = __shfl_sync(FULL, sc, j);
            int   nj = __shfl_sync(FULL, ci, j);
            bool prec = (sj > sc) || (sj == sc && nj < ci);
            if (j < M && prec) rank++;
        }
        if (act) ord[rank] = lane;            // lane holding rank r
        __syncwarp();

        // suppression mask over RANK bits: ranks I would suppress (rank_j > my rank)
        unsigned mymask = 0;
        #pragma unroll
        for (int j = 0; j < 32; j++) {
            float jx1 = __shfl_sync(FULL, x1, j);
            float jy1 = __shfl_sync(FULL, y1, j);
            float jx2 = __shfl_sync(FULL, x2, j);
            float jy2 = __shfl_sync(FULL, y2, j);
            float jar = __shfl_sync(FULL, area, j);
            int   jrk = __shfl_sync(FULL, rank, j);
            if (act && j < M) {
                float iou = iou_f(x1, y1, x2, y2, area, jx1, jy1, jx2, jy2, jar);
                if (iou > NMS_THRESH_F && jrk > rank) mymask |= 1u << jrk;
            }
        }
        // reorder masks into rank order: lane r gets mask of the rank-r box
        int srcl = (lane < M) ? ord[lane] : 0;
        unsigned maskr = __shfl_sync(FULL, mymask, srcl);

        // greedy resolve over bitmasks (all lanes redundantly)
        unsigned keepb = (M == 32) ? 0xffffffffu : ((1u << M) - 1u);
        for (int r = 0; r < M; r++) {
            unsigned mr = __shfl_sync(FULL, maskr, r);
            if (keepb & (1u << r)) keepb &= ~mr;
        }
        // M <= 32 < TOPN_PER_CLS: no per-class cap needed
        if (act && ((keepb >> rank) & 1u)) drow[ci] = sc;
        return;
    }

    // ---------------- block fallback path (M > 32) --------------------------
    if (tid < M) {
        int n = cn[tid];
        const float* pb = props + (b * NN + n) * 4;
        const float* rg = reg + (size_t)(((b * NN + n) * CC) + c) * 4;
        decode_clip(pb, rg, bx1[tid], by1[tid], bx2[tid], by2[tid]);
        bar[tid] = (bx2[tid] - bx1[tid] + 1.0f) * (by2[tid] - by1[tid] + 1.0f);
        keep[tid] = 1;
        ord[tid] = tid;
    }
    int P = 1;
    while (P < M) P <<= 1;
    if (tid >= M && tid < P) { cs[tid] = -INFINITY; cn[tid] = 1 << 30; ord[tid] = tid; }
    __syncthreads();

    // bitonic argsort: descending score, ascending original index
    for (int k = 2; k <= P; k <<= 1) {
        for (int j = k >> 1; j > 0; j >>= 1) {
            if (tid < P) {
                int ixj = tid ^ j;
                if (ixj > tid) {
                    int a = ord[tid], bo = ord[ixj];
                    float sa = cs[a], sb = cs[bo];
                    bool pa = (sa > sb) || (sa == sb && cn[a] < cn[bo]);
                    bool desc = ((tid & k) == 0);
                    bool sw = desc ? !pa : pa;
                    if (sw) { ord[tid] = bo; ord[ixj] = a; }
                }
            }
            __syncthreads();
        }
    }

    // greedy NMS in sorted order (float IoU)
    for (int i = 0; i < M - 1; i++) {
        __syncthreads();
        int oi = ord[i];
        if (!keep[oi]) continue;   // shared value: uniform branch
        float ax1 = bx1[oi], ay1 = by1[oi], ax2 = bx2[oi], ay2 = by2[oi], aar = bar[oi];
        for (int t = i + 1 + tid; t < M; t += 512) {
            int ot = ord[t];
            if (!keep[ot]) continue;
            float iou = iou_f(ax1, ay1, ax2, ay2, aar,
                              bx1[ot], by1[ot], bx2[ot], by2[ot], bar[ot]);
            if (iou > NMS_THRESH_F) keep[ot] = 0;
        }
    }
    __syncthreads();

    // per-class top-300 cap in sorted order
    if (tid == 0) {
        int cum = 0;
        for (int t = 0; t < M; t++) {
            int ot = ord[t];
            if (keep[ot]) { if (++cum > TOPN_PER_CLS) keep[ot] = 0; }
        }
    }
    __syncthreads();

    if (tid < M && keep[tid]) drow[cn[tid]] = cs[tid];
}

// ---------------------------------------------------------------------------
// K3: per image: argmax over classes, top-100 threshold, winner box decode
// ---------------------------------------------------------------------------
__global__ __launch_bounds__(512) void k_select(const float* __restrict__ reg,
                                                const float* __restrict__ props,
                                                float* __restrict__ out)
{
    int b = blockIdx.x;
    int n = threadIdx.x;

    float best = 0.f; int lab = 0;
    const float* dbase = g_dist + (size_t)b * CC * NN + n;
    #pragma unroll 4
    for (int c = 1; c < CC; c++) {
        float d = dbase[c << 9];
        if (d > best) { best = d; lab = c; }   // strict > == first-index argmax
    }
    bool v0 = best > 0.f;

    __shared__ float ss[NN];
    __shared__ int cnt;
    if (n == 0) cnt = 0;
    __syncthreads();
    ss[n] = v0 ? best : -1.0f;
    if (v0) atomicAdd(&cnt, 1);
    __syncthreads();

    // bitonic descending sort of 512 floats
    for (int k = 2; k <= NN; k <<= 1) {
        for (int j = k >> 1; j > 0; j >>= 1) {
            int ixj = n ^ j;
            if (ixj > n) {
                float a = ss[n], bb2 = ss[ixj];
                bool desc = ((n & k) == 0);
                bool sw = desc ? (a < bb2) : (a > bb2);
                if (sw) { ss[n] = bb2; ss[ixj] = a; }
            }
            __syncthreads();
        }
    }
    float kth = ss[DET_PER_IMG - 1];
    float thr = (cnt > DET_PER_IMG) ? kth : -1.0f;
    bool det = v0 && (best >= thr);

    float X1 = 0.f, Y1 = 0.f, X2 = 0.f, Y2 = 0.f, sc = 0.f, lb = 0.f, dv = 0.f;
    if (det) {
        const float* pb = props + (b * NN + n) * 4;
        const float* rg = reg + (size_t)(((b * NN + n) * CC) + lab) * 4;
        decode_clip(pb, rg, X1, Y1, X2, Y2);
        sc = best; lb = (float)lab; dv = 1.f;
    }
    int idx = b * NN + n;
    out[OFF_BOXES + idx * 4 + 0] = X1;
    out[OFF_BOXES + idx * 4 + 1] = Y1;
    out[OFF_BOXES + idx * 4 + 2] = X2;
    out[OFF_BOXES + idx * 4 + 3] = Y2;
    out[OFF_SCORES + idx] = sc;
    out[OFF_LABELS + idx] = lb;
    out[OFF_VALID  + idx] = dv;
    g_validf[idx] = dv;
}

// ---------------------------------------------------------------------------
// K4: features * det_valid  (memory-bound, float4)
// ---------------------------------------------------------------------------
__global__ __launch_bounds__(256) void k_feats(const float4* __restrict__ f,
                                               float4* __restrict__ out)
{
    int i = blockIdx.x * blockDim.x + threadIdx.x;
    if (i >= SZ_FEATS / 4) return;
    float m = g_validf[i >> 10];     // DD/4 = 1024 float4 per row
    float4 v = f[i];
    v.x *= m; v.y *= m; v.z *= m; v.w *= m;
    out[i] = v;
}

// ---------------------------------------------------------------------------
extern "C" void kernel_launch(void* const* d_in, const int* in_sizes, int n_in,
                              void* d_out, int out_size)
{
    const float *logits = nullptr, *reg = nullptr, *props = nullptr, *feats = nullptr;
    for (int i = 0; i < n_in; i++) {
        switch (in_sizes[i]) {
            case SZ_LOGITS: logits = (const float*)d_in[i]; break;
            case SZ_REG:    reg    = (const float*)d_in[i]; break;
            case SZ_PROPS:  props  = (const float*)d_in[i]; break;
            case SZ_FEATS:  feats  = (const float*)d_in[i]; break;
            default: break;
        }
    }
    float* out = (float*)d_out;

    k_softmax<<<128, 256>>>(logits);
    k_nms<<<BB * CC, 512>>>(reg, props);
    k_select<<<BB, 512>>>(reg, props, out);
    k_feats<<<(SZ_FEATS / 4 + 255) / 256, 256>>>((const float4*)feats,
                                                 (float4*)(out + OFF_FEATS));
    (void)out_size;
}

// round 8
// speedup vs baseline: 3.3100x; 1.3380x over previous
#include <cuda_runtime.h>
#include <math.h>

// Problem constants
#define BB 2
#define NN 512
#define CC 151
#define DD 4096
#define SCORE_THRESH 0.05f
#define NMS_THRESH_F 0.5f
#define TOPN_PER_CLS 300
#define DET_PER_IMG 100
#define W_CLIP 799.0f
#define H_CLIP 599.0f

// input element counts (for pointer identification)
#define SZ_LOGITS (BB*NN*CC)       // 154624
#define SZ_REG    (BB*NN*CC*4)     // 618496
#define SZ_PROPS  (BB*NN*4)        // 4096
#define SZ_FEATS  (BB*NN*DD)       // 4194304

// output layout (float32)
#define OFF_BOXES  0
#define OFF_SCORES (BB*NN*4)            // 4096
#define OFF_LABELS (OFF_SCORES + BB*NN) // 5120
#define OFF_VALID  (OFF_LABELS + BB*NN) // 6144
#define OFF_FEATS  (OFF_VALID + BB*NN)  // 7168

// scratch (device globals; no allocation allowed)
__device__ float g_prob[BB*CC*NN];                 // [b][c][n]
__device__ unsigned long long g_best[BB*NN];       // packed (score_bits<<32)|(CC-label)
__device__ float g_validf[BB*NN];                  // 1.0/0.0 mask for features

// ---------------------------------------------------------------------------
// decode stays double (few K calls; feeds output boxes + IoU inputs)
// ---------------------------------------------------------------------------
__device__ __forceinline__ void decode_clip(const float* pb, const float* rg,
                                            float& X1, float& Y1, float& X2, float& Y2)
{
    const double DCLAMP = (double)(float)log(62.5);  // float(np.log(1000/16))
    double x1 = pb[0], y1 = pb[1], x2 = pb[2], y2 = pb[3];
    double w = x2 - x1 + 1.0, h = y2 - y1 + 1.0;
    double cx = x1 + 0.5 * w, cy = y1 + 0.5 * h;
    double dx = (double)rg[0] / 10.0;
    double dy = (double)rg[1] / 10.0;
    double dw = fmin((double)rg[2] / 5.0, DCLAMP);
    double dh = fmin((double)rg[3] / 5.0, DCLAMP);
    double pcx = dx * w + cx, pcy = dy * h + cy;
    double pw = exp(dw) * w, ph = exp(dh) * h;
    float a = (float)(pcx - 0.5 * pw);
    float b = (float)(pcy - 0.5 * ph);
    float c = (float)(pcx + 0.5 * pw - 1.0);
    float d = (float)(pcy + 0.5 * ph - 1.0);
    X1 = fminf(fmaxf(a, 0.f), W_CLIP);
    Y1 = fminf(fmaxf(b, 0.f), H_CLIP);
    X2 = fminf(fmaxf(c, 0.f), W_CLIP);
    Y2 = fminf(fmaxf(d, 0.f), H_CLIP);
}

// float IoU, exact reference formula order (Pascal +1 convention)
__device__ __forceinline__ float iou_f(float ax1, float ay1, float ax2, float ay2, float areaA,
                                       float bx1, float by1, float bx2, float by2, float areaB)
{
    float xx1 = fmaxf(ax1, bx1);
    float yy1 = fmaxf(ay1, by1);
    float xx2 = fminf(ax2, bx2);
    float yy2 = fminf(ay2, by2);
    float inter = fmaxf(xx2 - xx1 + 1.0f, 0.0f) * fmaxf(yy2 - yy1 + 1.0f, 0.0f);
    return inter / (areaA + areaB - inter);
}

__device__ __forceinline__ unsigned long long pack_sl(float s, int c)
{
    return ((unsigned long long)__float_as_uint(s) << 32) | (unsigned)(CC - c);
}

// ---------------------------------------------------------------------------
// K1: softmax, one warp per (b,n) row, fp32, shfl reductions; zero g_best
// ---------------------------------------------------------------------------
__global__ __launch_bounds__(256) void k_softmax(const float* __restrict__ logits)
{
    int gidx = blockIdx.x * 256 + threadIdx.x;
    if (gidx < BB * NN) g_best[gidx] = 0ull;

    int gw = blockIdx.x * 8 + (threadIdx.x >> 5);   // 128 blocks * 8 warps = 1024 rows
    int lane = threadIdx.x & 31;
    if (gw >= BB * NN) return;
    int b = gw >> 9, n = gw & 511;
    const float* lrow = logits + gw * CC;
    float x[5];
    float m = -INFINITY;
    #pragma unroll
    for (int j = 0; j < 5; j++) {
        int c = lane + 32 * j;
        x[j] = (c < CC) ? lrow[c] : -INFINITY;
        m = fmaxf(m, x[j]);
    }
    #pragma unroll
    for (int s = 16; s > 0; s >>= 1)
        m = fmaxf(m, __shfl_xor_sync(0xffffffffu, m, s));
    float e[5], sum = 0.f;
    #pragma unroll
    for (int j = 0; j < 5; j++) {
        int c = lane + 32 * j;
        e[j] = (c < CC) ? expf(x[j] - m) : 0.f;
        sum += e[j];
    }
    #pragma unroll
    for (int s = 16; s > 0; s >>= 1)
        sum += __shfl_xor_sync(0xffffffffu, sum, s);
    float inv = 1.f / sum;
    #pragma unroll
    for (int j = 0; j < 5; j++) {
        int c = lane + 32 * j;
        if (c < CC)
            g_prob[((b * CC + c) << 9) + n] = e[j] * inv;
    }
}

// ---------------------------------------------------------------------------
// K2: per (b,c) NMS -> atomicMax into g_best
// ---------------------------------------------------------------------------
__global__ __launch_bounds__(512) void k_nms(const float* __restrict__ reg,
                                             const float* __restrict__ props)
{
    int blk = blockIdx.x;           // b*(CC-1) + (c-1): background class skipped
    int b = blk / (CC - 1), c = blk % (CC - 1) + 1;
    int tid = threadIdx.x;

    const float* prow = g_prob + ((b * CC + c) << 9);

    float s = prow[tid];

    __shared__ int cnt;
    __shared__ float cs[NN];
    __shared__ int   cn[NN];
    __shared__ float bx1[NN], by1[NN], bx2[NN], by2[NN], bar[NN];
    __shared__ short rankOf[NN];
    __shared__ int   ord[NN];
    __shared__ unsigned char keep[NN];
    __shared__ unsigned smask[128][4];

    if (tid == 0) cnt = 0;
    __syncthreads();

    int slot = -1;
    if (s > SCORE_THRESH) slot = atomicAdd(&cnt, 1);
    if (slot >= 0) { cs[slot] = s; cn[slot] = tid; }
    __syncthreads();

    int M = cnt;
    if (M == 0) return;

    if (M <= 128) {
        // ---- unified shared-memory path: ~3 barriers total ------------------
        if (tid < M) {
            int n = cn[tid];
            const float* pb = props + (b * NN + n) * 4;
            const float* rg = reg + (size_t)(((b * NN + n) * CC) + c) * 4;
            decode_clip(pb, rg, bx1[tid], by1[tid], bx2[tid], by2[tid]);
            bar[tid] = (bx2[tid] - bx1[tid] + 1.0f) * (by2[tid] - by1[tid] + 1.0f);
            // rank: descending score, ties -> ascending original index
            float ms = cs[tid]; int mn = cn[tid];
            int r = 0;
            for (int j = 0; j < M; j++) {
                float sj = cs[j]; int nj = cn[j];
                if ((sj > ms) || (sj == ms && nj < mn)) r++;
            }
            rankOf[tid] = (short)r;
            smask[tid][0] = 0; smask[tid][1] = 0;
            smask[tid][2] = 0; smask[tid][3] = 0;
        }
        __syncthreads();

        // all-pairs IoU into rank-space suppression masks
        for (int p = tid; p < M * M; p += 512) {
            int i = p / M, j = p - i * M;
            int ri = rankOf[i], rj = rankOf[j];
            if (rj > ri) {
                float iou = iou_f(bx1[i], by1[i], bx2[i], by2[i], bar[i],
                                  bx1[j], by1[j], bx2[j], by2[j], bar[j]);
                if (iou > NMS_THRESH_F)
                    atomicOr(&smask[ri][rj >> 5], 1u << (rj & 31));
            }
        }
        __syncthreads();

        // redundant greedy resolve in registers (broadcast smem reads)
        unsigned k0, k1, k2, k3;
        k0 = (M >= 32)  ? 0xffffffffu : ((1u << M) - 1u);
        k1 = (M >= 64)  ? 0xffffffffu : (M > 32 ? ((1u << (M - 32)) - 1u) : 0u);
        k2 = (M >= 96)  ? 0xffffffffu : (M > 64 ? ((1u << (M - 64)) - 1u) : 0u);
        k3 = (M >= 128) ? 0xffffffffu : (M > 96 ? ((1u << (M - 96)) - 1u) : 0u);
        for (int r = 0; r < M; r++) {
            unsigned kw = (r < 32) ? k0 : (r < 64) ? k1 : (r < 96) ? k2 : k3;
            if ((kw >> (r & 31)) & 1u) {
                k0 &= ~smask[r][0];
                k1 &= ~smask[r][1];
                k2 &= ~smask[r][2];
                k3 &= ~smask[r][3];
            }
        }
        // M <= 128 < TOPN_PER_CLS: no per-class cap needed
        if (tid < M) {
            int r = rankOf[tid];
            unsigned kw = (r < 32) ? k0 : (r < 64) ? k1 : (r < 96) ? k2 : k3;
            if ((kw >> (r & 31)) & 1u)
                atomicMax(&g_best[b * NN + cn[tid]], pack_sl(cs[tid], c));
        }
        return;
    }

    // ---- legacy block path (M > 128, essentially never) ---------------------
    if (tid < M) {
        int n = cn[tid];
        const float* pb = props + (b * NN + n) * 4;
        const float* rg = reg + (size_t)(((b * NN + n) * CC) + c) * 4;
        decode_clip(pb, rg, bx1[tid], by1[tid], bx2[tid], by2[tid]);
        bar[tid] = (bx2[tid] - bx1[tid] + 1.0f) * (by2[tid] - by1[tid] + 1.0f);
        keep[tid] = 1;
        ord[tid] = tid;
    }
    int P = 1;
    while (P < M) P <<= 1;
    if (tid >= M && tid < P) { cs[tid] = -INFINITY; cn[tid] = 1 << 30; ord[tid] = tid; }
    __syncthreads();

    for (int k = 2; k <= P; k <<= 1) {
        for (int j = k >> 1; j > 0; j >>= 1) {
            if (tid < P) {
                int ixj = tid ^ j;
                if (ixj > tid) {
                    int a = ord[tid], bo = ord[ixj];
                    float sa = cs[a], sb = cs[bo];
                    bool pa = (sa > sb) || (sa == sb && cn[a] < cn[bo]);
                    bool desc = ((tid & k) == 0);
                    bool sw = desc ? !pa : pa;
                    if (sw) { ord[tid] = bo; ord[ixj] = a; }
                }
            }
            __syncthreads();
        }
    }

    for (int i = 0; i < M - 1; i++) {
        __syncthreads();
        int oi = ord[i];
        if (!keep[oi]) continue;
        float ax1 = bx1[oi], ay1 = by1[oi], ax2 = bx2[oi], ay2 = by2[oi], aar = bar[oi];
        for (int t = i + 1 + tid; t < M; t += 512) {
            int ot = ord[t];
            if (!keep[ot]) continue;
            float iou = iou_f(ax1, ay1, ax2, ay2, aar,
                              bx1[ot], by1[ot], bx2[ot], by2[ot], bar[ot]);
            if (iou > NMS_THRESH_F) keep[ot] = 0;
        }
    }
    __syncthreads();

    if (tid == 0) {
        int cum = 0;
        for (int t = 0; t < M; t++) {
            int ot = ord[t];
            if (keep[ot]) { if (++cum > TOPN_PER_CLS) keep[ot] = 0; }
        }
    }
    __syncthreads();

    if (tid < M && keep[tid])
        atomicMax(&g_best[b * NN + cn[tid]], pack_sl(cs[tid], c));
}

// ---------------------------------------------------------------------------
// K3: per image: unpack winners, top-100 threshold via rank counting,
//     decode winner box, write outputs
// ---------------------------------------------------------------------------
__global__ __launch_bounds__(512) void k_select(const float* __restrict__ reg,
                                                const float* __restrict__ props,
                                                float* __restrict__ out)
{
    int b = blockIdx.x;
    int n = threadIdx.x;

    unsigned long long pk = g_best[b * NN + n];
    float best = __uint_as_float((unsigned)(pk >> 32));
    int   lab  = CC - (int)(pk & 0xffffffffu);      // valid only when pk != 0
    bool  v0   = pk != 0ull;                        // best > 0

    __shared__ float vals[NN];
    __shared__ float wmin[16];
    vals[n] = v0 ? best : -1.0f;
    int num = __syncthreads_count(v0);

    // rank = #{j : vals[j] > mine}; broadcast smem reads, no barriers
    float myv = vals[n];
    int rk = 0;
    #pragma unroll 8
    for (int j = 0; j < NN; j++)
        rk += (vals[j] > myv);

    // kth-largest = min{v : rank <= 99}
    float cand = (rk <= DET_PER_IMG - 1) ? myv : INFINITY;
    #pragma unroll
    for (int s = 16; s > 0; s >>= 1)
        cand = fminf(cand, __shfl_xor_sync(0xffffffffu, cand, s));
    if ((n & 31) == 0) wmin[n >> 5] = cand;
    __syncthreads();
    if (n < 32) {
        float c2 = (n < 16) ? wmin[n] : INFINITY;
        #pragma unroll
        for (int s = 8; s > 0; s >>= 1)
            c2 = fminf(c2, __shfl_xor_sync(0xffffffffu, c2, s));
        if (n == 0) wmin[0] = c2;
    }
    __syncthreads();
    float thr = (num > DET_PER_IMG) ? wmin[0] : -1.0f;
    bool det = v0 && (best >= thr);

    float X1 = 0.f, Y1 = 0.f, X2 = 0.f, Y2 = 0.f, sc = 0.f, lb = 0.f, dv = 0.f;
    if (det) {
        const float* pb = props + (b * NN + n) * 4;
        const float* rg = reg + (size_t)(((b * NN + n) * CC) + lab) * 4;
        decode_clip(pb, rg, X1, Y1, X2, Y2);
        sc = best; lb = (float)lab; dv = 1.f;
    }
    int idx = b * NN + n;
    out[OFF_BOXES + idx * 4 + 0] = X1;
    out[OFF_BOXES + idx * 4 + 1] = Y1;
    out[OFF_BOXES + idx * 4 + 2] = X2;
    out[OFF_BOXES + idx * 4 + 3] = Y2;
    out[OFF_SCORES + idx] = sc;
    out[OFF_LABELS + idx] = lb;
    out[OFF_VALID  + idx] = dv;
    g_validf[idx] = dv;
}

// ---------------------------------------------------------------------------
// K4: features * det_valid  (memory-bound, float4)
// ---------------------------------------------------------------------------
__global__ __launch_bounds__(256) void k_feats(const float4* __restrict__ f,
                                               float4* __restrict__ out)
{
    int i = blockIdx.x * blockDim.x + threadIdx.x;
    if (i >= SZ_FEATS / 4) return;
    float m = g_validf[i >> 10];     // DD/4 = 1024 float4 per row
    float4 v = f[i];
    v.x *= m; v.y *= m; v.z *= m; v.w *= m;
    out[i] = v;
}

// ---------------------------------------------------------------------------
extern "C" void kernel_launch(void* const* d_in, const int* in_sizes, int n_in,
                              void* d_out, int out_size)
{
    const float *logits = nullptr, *reg = nullptr, *props = nullptr, *feats = nullptr;
    for (int i = 0; i < n_in; i++) {
        switch (in_sizes[i]) {
            case SZ_LOGITS: logits = (const float*)d_in[i]; break;
            case SZ_REG:    reg    = (const float*)d_in[i]; break;
            case SZ_PROPS:  props  = (const float*)d_in[i]; break;
            case SZ_FEATS:  feats  = (const float*)d_in[i]; break;
            default: break;
        }
    }
    float* out = (float*)d_out;

    k_softmax<<<128, 256>>>(logits);
    k_nms<<<BB * (CC - 1), 512>>>(reg, props);
    k_select<<<BB, 512>>>(reg, props, out);
    k_feats<<<(SZ_FEATS / 4 + 255) / 256, 256>>>((const float4*)feats,
                                                 (float4*)(out + OFF_FEATS));
    (void)out_size;
}